// round 13
// baseline (speedup 1.0000x reference)
#include <cuda_runtime.h>
#include <cuda_fp16.h>
#include <cstdint>

#define BATCH 8
#define NTOK  1024
#define CH    512
#define NHEAD 16
#define HD    32
#define LOG2E 1.4426950408889634f
#define QSC (0.17677669529663689f * 1.4426950408889634f)

// fp16 scratch
__device__ __half g_xh[BATCH * NTOK * CH];
__device__ __half g_wqh[3 * CH * CH];
__device__ __half g_pwh[CH * CH];
__device__ __half g_q[BATCH * NHEAD * NTOK * HD];
__device__ __half g_k[BATCH * NHEAD * NTOK * HD];
__device__ __half g_v[BATCH * NHEAD * NTOK * HD];
__device__ __half g_oh[BATCH * NTOK * CH];

__device__ __forceinline__ uint32_t smem_u32(const void* p) {
    return (uint32_t)__cvta_generic_to_shared(p);
}
__device__ __forceinline__ void cp16(void* sdst, const void* gsrc) {
    asm volatile("cp.async.cg.shared.global [%0], [%1], 16;"
                 :: "r"(smem_u32(sdst)), "l"(gsrc));
}
#define CP_COMMIT() asm volatile("cp.async.commit_group;" ::: "memory")
#define CP_WAIT0()  asm volatile("cp.async.wait_group 0;" ::: "memory")
#define CP_WAIT1()  asm volatile("cp.async.wait_group 1;" ::: "memory")

__device__ __forceinline__ void ldm_x4(uint32_t* r, uint32_t a) {
    asm volatile("ldmatrix.sync.aligned.m8n8.x4.shared.b16 {%0,%1,%2,%3}, [%4];"
                 : "=r"(r[0]), "=r"(r[1]), "=r"(r[2]), "=r"(r[3]) : "r"(a));
}
__device__ __forceinline__ void ldm_x4_t(uint32_t* r, uint32_t a) {
    asm volatile("ldmatrix.sync.aligned.m8n8.x4.trans.shared.b16 {%0,%1,%2,%3}, [%4];"
                 : "=r"(r[0]), "=r"(r[1]), "=r"(r[2]), "=r"(r[3]) : "r"(a));
}
__device__ __forceinline__ void mma16816(float* c, const uint32_t* a, const uint32_t* b) {
    asm volatile(
        "mma.sync.aligned.m16n8k16.row.col.f32.f16.f16.f32 "
        "{%0,%1,%2,%3}, {%4,%5,%6,%7}, {%8,%9}, {%0,%1,%2,%3};"
        : "+f"(c[0]), "+f"(c[1]), "+f"(c[2]), "+f"(c[3])
        : "r"(a[0]), "r"(a[1]), "r"(a[2]), "r"(a[3]), "r"(b[0]), "r"(b[1]));
}

// ---------------------------------------------------------------------------
// Kernel 0: fp32 -> fp16 conversion of X, qkv_w, proj_w.
// ---------------------------------------------------------------------------
#define NX4  (BATCH * NTOK * CH / 4)
#define NWQ4 (3 * CH * CH / 4)
#define NWP4 (CH * CH / 4)

__global__ __launch_bounds__(256) void convert_all(const float4* __restrict__ X,
                                                   const float4* __restrict__ Wq,
                                                   const float4* __restrict__ Wp)
{
    int i = blockIdx.x * 256 + threadIdx.x;
    const float4* src;
    __half2* dst;
    int j;
    if (i < NX4)                    { src = X;  dst = (__half2*)g_xh;  j = i; }
    else if (i < NX4 + NWQ4)        { src = Wq; dst = (__half2*)g_wqh; j = i - NX4; }
    else if (i < NX4 + NWQ4 + NWP4) { src = Wp; dst = (__half2*)g_pwh; j = i - NX4 - NWQ4; }
    else return;
    float4 v = __ldg(src + j);
    dst[2 * j]     = __floats2half2_rn(v.x, v.y);
    dst[2 * j + 1] = __floats2half2_rn(v.z, v.w);
}

// ---------------------------------------------------------------------------
// HMMA GEMM: 128x128 tile, 8 warps (32x64 each), K-chunk 32.
// 4-stage cp.async ring (copies 3 ahead) + cross-iteration FRAGMENT pipeline:
// at iteration kc, stage kc+1's data is guaranteed resident (CP_WAIT1), so its
// LDSMs are issued alongside kc's 64 MMAs -> tensor stream never waits on LDSM.
// Stage s: A at s*20480, B at s*20480+10240.  Total dyn smem 81920.
// ---------------------------------------------------------------------------
#define G_STAGE 20480
#define G_SMEM  81920

__global__ __launch_bounds__(256, 2) void hgemm(const float* __restrict__ bias,
                                                float* __restrict__ out32,
                                                int mode)
{
    extern __shared__ __align__(16) char dsm[];

    const __half* Aptr = mode ? g_oh  : g_xh;
    const __half* Bptr = mode ? g_pwh : g_wqh;

    const int tid = threadIdx.x, lane = tid & 31, w = tid >> 5;
    const int wm = w >> 1, wn = w & 1;
    const int m0 = blockIdx.y * 128, n0 = blockIdx.x * 128;

    float acc[2][8][4];
#pragma unroll
    for (int mt = 0; mt < 2; mt++)
#pragma unroll
        for (int nt = 0; nt < 8; nt++)
#pragma unroll
            for (int c = 0; c < 4; c++) acc[mt][nt][c] = 0.f;

    const int a_row  = wm * 32 + (lane & 15);
    const int a_colh = (lane >> 4) * 8;
    const int b_row  = wn * 64 + (lane & 7) + ((lane >> 4) << 3);
    const int b_colh = ((lane >> 3) & 1) * 8;
    const int cr = tid >> 2, cc = (tid & 3) * 8;

    auto docopy = [&](int kc, int s) {
        char* Ab = dsm + s * G_STAGE;
        char* Bb = Ab + 10240;
#pragma unroll
        for (int i = 0; i < 2; i++) {
            int r = cr + i * 64;
            cp16(Ab + r * 80 + cc * 2, Aptr + (size_t)(m0 + r) * CH + kc * 32 + cc);
            cp16(Bb + r * 80 + cc * 2, Bptr + (size_t)(n0 + r) * CH + kc * 32 + cc);
        }
    };

    // fragment loader for one K-chunk (both ks slices) into buffer fb
    uint32_t aF[2][2][2][4];   // [fb][ks][mt][4]
    uint32_t bF[2][2][8][2];   // [fb][ks][nt][2]
    auto loadfrag = [&](int kc, int fb) {
        char* Ab = dsm + (kc & 3) * G_STAGE;
        char* Bb = Ab + 10240;
#pragma unroll
        for (int ks = 0; ks < 2; ks++) {
#pragma unroll
            for (int mt = 0; mt < 2; mt++)
                ldm_x4(aF[fb][ks][mt], smem_u32(Ab + (a_row + mt * 16) * 80
                                                   + (ks * 16 + a_colh) * 2));
#pragma unroll
            for (int q = 0; q < 4; q++) {
                uint32_t r[4];
                ldm_x4(r, smem_u32(Bb + (b_row + q * 16) * 80
                                      + (ks * 16 + b_colh) * 2));
                bF[fb][ks][2 * q][0] = r[0]; bF[fb][ks][2 * q][1] = r[1];
                bF[fb][ks][2 * q + 1][0] = r[2]; bF[fb][ks][2 * q + 1][1] = r[3];
            }
        }
    };

    docopy(0, 0); CP_COMMIT();
    docopy(1, 1); CP_COMMIT();
    docopy(2, 2); CP_COMMIT();

    for (int kc = 0; kc < 16; kc++) {
        if (kc < 14) { CP_WAIT1(); } else { CP_WAIT0(); }
        __syncthreads();
        if (kc + 3 < 16) { docopy(kc + 3, (kc + 3) & 3); CP_COMMIT(); }

        if (kc == 0) loadfrag(0, 0);
        const int fb = kc & 1;
        if (kc + 1 < 16) loadfrag(kc + 1, fb ^ 1);   // overlaps with MMAs below

#pragma unroll
        for (int ks = 0; ks < 2; ks++)
#pragma unroll
            for (int mt = 0; mt < 2; mt++)
#pragma unroll
                for (int nt = 0; nt < 8; nt++)
                    mma16816(acc[mt][nt], aF[fb][ks][mt], bF[fb][ks][nt]);
    }

    const int qr = lane >> 2, qc = (lane & 3) * 2;
    if (mode == 0) {
#pragma unroll
        for (int mt = 0; mt < 2; mt++) {
#pragma unroll
            for (int nt = 0; nt < 8; nt++) {
                int jj = n0 + wn * 64 + nt * 8 + qc;
                float b0 = __ldg(&bias[jj]), b1 = __ldg(&bias[jj + 1]);
                int which = jj >> 9, h = (jj >> 5) & 15, dd = jj & 31;
#pragma unroll
                for (int rr = 0; rr < 2; rr++) {
                    int m = m0 + wm * 32 + mt * 16 + qr + rr * 8;
                    int b = m >> 10, n = m & 1023;
                    float v0 = acc[mt][nt][rr * 2 + 0] + b0;
                    float v1 = acc[mt][nt][rr * 2 + 1] + b1;
                    if (which == 0) { v0 *= QSC; v1 *= QSC; }
                    __half2 hv = __floats2half2_rn(v0, v1);
                    size_t off = ((size_t)(b * NHEAD + h) * NTOK + n) * HD + dd;
                    if (which == 0)      *(__half2*)&g_q[off] = hv;
                    else if (which == 1) *(__half2*)&g_k[off] = hv;
                    else                 *(__half2*)&g_v[off] = hv;
                }
            }
        }
    } else {
#pragma unroll
        for (int mt = 0; mt < 2; mt++) {
#pragma unroll
            for (int nt = 0; nt < 8; nt++) {
                int jj = n0 + wn * 64 + nt * 8 + qc;
                float b0 = __ldg(&bias[jj]), b1 = __ldg(&bias[jj + 1]);
#pragma unroll
                for (int rr = 0; rr < 2; rr++) {
                    int m = m0 + wm * 32 + mt * 16 + qr + rr * 8;
                    float2 v = make_float2(acc[mt][nt][rr * 2 + 0] + b0,
                                           acc[mt][nt][rr * 2 + 1] + b1);
                    *(float2*)&out32[(size_t)m * CH + jj] = v;
                }
            }
        }
    }
}

// ---------------------------------------------------------------------------
// Kernel 2: attention (round-8 proven version, unchanged).
// ---------------------------------------------------------------------------
#define AT_QS   0
#define AT_KS   10240
#define AT_VS   25600
#define AT_RPB  40960
#define AT_SMEM 56960

__global__ __launch_bounds__(256) void attn_kernel(const float* __restrict__ rpb)
{
    extern __shared__ __align__(16) char dsm[];
    __half* Qs    = (__half*)(dsm + AT_QS);
    float*  rpb_s = (float*)(dsm + AT_RPB);

    const int bh = blockIdx.x;
    const int b  = bh >> 4, h = bh & 15;
    const int qbase = blockIdx.y * 128;
    const int tid = threadIdx.x, lane = tid & 31, w = tid >> 5;

    const int cr = tid >> 2, cc = (tid & 3) * 8;
    const __half* kbase = g_k + (size_t)bh * NTOK * HD;
    const __half* vbase = g_v + (size_t)bh * NTOK * HD;

    auto copy_kv = [&](int kt, int s) {
        char* Kb = dsm + AT_KS + s * 5120;
        char* Vb = dsm + AT_VS + s * 5120;
        cp16(Kb + cr * 80 + cc * 2, kbase + (size_t)(kt * 64 + cr) * HD + cc);
        cp16(Vb + cr * 80 + cc * 2, vbase + (size_t)(kt * 64 + cr) * HD + cc);
    };

    copy_kv(0, 0); CP_COMMIT();
    copy_kv(1, 1); CP_COMMIT();

    for (int e = tid; e < 3969; e += 256)
        rpb_s[e] = __ldg(rpb + (size_t)h * 3969 + e) * LOG2E;

    const __half* qg = g_q + ((size_t)bh * NTOK + qbase) * HD;
#pragma unroll
    for (int i = 0; i < 2; i++) {
        int e = tid + i * 256;
        int row = e >> 2, c8 = (e & 3) * 8;
        *(uint4*)(Qs + row * 40 + c8) = *(const uint4*)(qg + row * HD + c8);
    }
    __syncthreads();

    uint32_t aQ[2][4];
#pragma unroll
    for (int ks = 0; ks < 2; ks++)
        ldm_x4(aQ[ks], smem_u32(Qs + (w * 16 + (lane & 15)) * 40
                                   + ks * 16 + (lane >> 4) * 8));

    const int qr = lane >> 2, qc = (lane & 3) * 2;
    const int i1 = qbase + w * 16 + qr, i2 = i1 + 8;
    const int off1 = (31 - (i1 >> 5)) * 63 + (31 - (i1 & 31));
    const int off2 = (31 - (i2 >> 5)) * 63 + (31 - (i2 & 31));

    float oacc[4][4];
    float lacc[4];
#pragma unroll
    for (int i = 0; i < 4; i++) {
        lacc[i] = 0.f;
#pragma unroll
        for (int c = 0; c < 4; c++) oacc[i][c] = 0.f;
    }

    uint32_t bones[2];
    bones[0] = bones[1] = (lane < 4) ? 0x3C003C00u : 0u;

    const int kb_row = (lane & 7) + ((lane >> 4) << 3);
    const int kb_col = ((lane >> 3) & 1) * 8;

    for (int kt = 0; kt < 16; kt++) {
        if (kt < 15) { CP_WAIT1(); } else { CP_WAIT0(); }
        __syncthreads();
        if (kt + 2 < 16) { copy_kv(kt + 2, (kt + 2) % 3); CP_COMMIT(); }

        const int s = kt % 3;
        char* Kb = dsm + AT_KS + s * 5120;
        char* Vb = dsm + AT_VS + s * 5120;

        float sc[8][4];
#pragma unroll
        for (int nt = 0; nt < 8; nt++) {
            int j0 = kt * 64 + nt * 8 + qc;
            int ja = j0 + 31 * (j0 >> 5);
            sc[nt][0] = rpb_s[off1 + ja];
            sc[nt][1] = rpb_s[off1 + ja + 1];
            sc[nt][2] = rpb_s[off2 + ja];
            sc[nt][3] = rpb_s[off2 + ja + 1];
        }

#pragma unroll
        for (int ks = 0; ks < 2; ks++) {
#pragma unroll
            for (int q = 0; q < 4; q++) {
                uint32_t r[4];
                ldm_x4(r, smem_u32(Kb + (q * 16 + kb_row) * 80
                                      + (ks * 16 + kb_col) * 2));
                uint32_t b0[2] = { r[0], r[1] }, b1[2] = { r[2], r[3] };
                mma16816(sc[2 * q],     aQ[ks], b0);
                mma16816(sc[2 * q + 1], aQ[ks], b1);
            }
        }

        uint32_t pexp[8][2];
#pragma unroll
        for (int nt = 0; nt < 8; nt++) {
            __half2 e0 = h2exp2(__floats2half2_rn(sc[nt][0], sc[nt][1]));
            __half2 e1 = h2exp2(__floats2half2_rn(sc[nt][2], sc[nt][3]));
            pexp[nt][0] = *(uint32_t*)&e0;
            pexp[nt][1] = *(uint32_t*)&e1;
        }

#pragma unroll
        for (int kk = 0; kk < 4; kk++) {
            uint32_t aP[4] = { pexp[2 * kk][0], pexp[2 * kk][1],
                               pexp[2 * kk + 1][0], pexp[2 * kk + 1][1] };
#pragma unroll
            for (int dp = 0; dp < 2; dp++) {
                uint32_t r[4];
                ldm_x4_t(r, smem_u32(Vb + (kk * 16 + (lane & 15)) * 80
                                        + (dp * 16 + (lane >> 4) * 8) * 2));
                uint32_t b0[2] = { r[0], r[1] }, b1[2] = { r[2], r[3] };
                mma16816(oacc[2 * dp],     aP, b0);
                mma16816(oacc[2 * dp + 1], aP, b1);
            }
            mma16816(lacc, aP, bones);
        }
    }

    float l1 = __shfl_sync(0xffffffffu, lacc[0], lane & ~3);
    float l2 = __shfl_sync(0xffffffffu, lacc[2], lane & ~3);

    float inv1 = 1.f / l1, inv2 = 1.f / l2;
#pragma unroll
    for (int ntd = 0; ntd < 4; ntd++) {
        int d0 = ntd * 8 + qc;
        *(__half2*)&g_oh[((size_t)b * NTOK + i1) * CH + h * HD + d0] =
            __floats2half2_rn(oacc[ntd][0] * inv1, oacc[ntd][1] * inv1);
        *(__half2*)&g_oh[((size_t)b * NTOK + i2) * CH + h * HD + d0] =
            __floats2half2_rn(oacc[ntd][2] * inv2, oacc[ntd][3] * inv2);
    }
}

// ---------------------------------------------------------------------------
extern "C" void kernel_launch(void* const* d_in, const int* in_sizes, int n_in,
                              void* d_out, int out_size)
{
    const float* x      = (const float*)d_in[0];
    const float* qkv_w  = (const float*)d_in[1];
    const float* qkv_b  = (const float*)d_in[2];
    const float* rpb    = (const float*)d_in[3];
    const float* proj_w = (const float*)d_in[4];
    const float* proj_b = (const float*)d_in[5];
    float* out = (float*)d_out;

    cudaFuncSetAttribute(hgemm, cudaFuncAttributeMaxDynamicSharedMemorySize, G_SMEM);
    cudaFuncSetAttribute(attn_kernel, cudaFuncAttributeMaxDynamicSharedMemorySize, AT_SMEM);

    convert_all<<<(NX4 + NWQ4 + NWP4 + 255) / 256, 256>>>(
        (const float4*)x, (const float4*)qkv_w, (const float4*)proj_w);
    hgemm<<<dim3(12, 64), 256, G_SMEM>>>(qkv_b, nullptr, 0);
    attn_kernel<<<dim3(BATCH * NHEAD, NTOK / 128), 256, AT_SMEM>>>(rpb);
    hgemm<<<dim3(4, 64), 256, G_SMEM>>>(proj_b, out, 1);
}

// round 14
// speedup vs baseline: 1.7451x; 1.7451x over previous
#include <cuda_runtime.h>
#include <cuda_fp16.h>
#include <cstdint>

#define BATCH 8
#define NTOK  1024
#define CH    512
#define NHEAD 16
#define HD    32
#define LOG2E 1.4426950408889634f
#define QSC (0.17677669529663689f * 1.4426950408889634f)

// fp16 scratch
__device__ __half g_xh[BATCH * NTOK * CH];
__device__ __half g_wqh[3 * CH * CH];
__device__ __half g_pwh[CH * CH];
__device__ __half g_q[BATCH * NHEAD * NTOK * HD];
__device__ __half g_k[BATCH * NHEAD * NTOK * HD];
__device__ __half g_v[BATCH * NHEAD * NTOK * HD];
__device__ __half g_oh[BATCH * NTOK * CH];

__device__ __forceinline__ uint32_t smem_u32(const void* p) {
    return (uint32_t)__cvta_generic_to_shared(p);
}
__device__ __forceinline__ void cp16(void* sdst, const void* gsrc) {
    asm volatile("cp.async.cg.shared.global [%0], [%1], 16;"
                 :: "r"(smem_u32(sdst)), "l"(gsrc));
}
#define CP_COMMIT() asm volatile("cp.async.commit_group;" ::: "memory")
#define CP_WAIT0()  asm volatile("cp.async.wait_group 0;" ::: "memory")
#define CP_WAIT1()  asm volatile("cp.async.wait_group 1;" ::: "memory")
#define CP_WAIT2()  asm volatile("cp.async.wait_group 2;" ::: "memory")

__device__ __forceinline__ void ldm_x4(uint32_t* r, uint32_t a) {
    asm volatile("ldmatrix.sync.aligned.m8n8.x4.shared.b16 {%0,%1,%2,%3}, [%4];"
                 : "=r"(r[0]), "=r"(r[1]), "=r"(r[2]), "=r"(r[3]) : "r"(a));
}
__device__ __forceinline__ void ldm_x4_t(uint32_t* r, uint32_t a) {
    asm volatile("ldmatrix.sync.aligned.m8n8.x4.trans.shared.b16 {%0,%1,%2,%3}, [%4];"
                 : "=r"(r[0]), "=r"(r[1]), "=r"(r[2]), "=r"(r[3]) : "r"(a));
}
__device__ __forceinline__ void mma16816(float* c, const uint32_t* a, const uint32_t* b) {
    asm volatile(
        "mma.sync.aligned.m16n8k16.row.col.f32.f16.f16.f32 "
        "{%0,%1,%2,%3}, {%4,%5,%6,%7}, {%8,%9}, {%0,%1,%2,%3};"
        : "+f"(c[0]), "+f"(c[1]), "+f"(c[2]), "+f"(c[3])
        : "r"(a[0]), "r"(a[1]), "r"(a[2]), "r"(a[3]), "r"(b[0]), "r"(b[1]));
}

// ---------------------------------------------------------------------------
// Kernel 0: fp32 -> fp16 conversion of X, qkv_w, proj_w.
// ---------------------------------------------------------------------------
#define NX4  (BATCH * NTOK * CH / 4)
#define NWQ4 (3 * CH * CH / 4)
#define NWP4 (CH * CH / 4)

__global__ __launch_bounds__(256) void convert_all(const float4* __restrict__ X,
                                                   const float4* __restrict__ Wq,
                                                   const float4* __restrict__ Wp)
{
    int i = blockIdx.x * 256 + threadIdx.x;
    const float4* src;
    __half2* dst;
    int j;
    if (i < NX4)                    { src = X;  dst = (__half2*)g_xh;  j = i; }
    else if (i < NX4 + NWQ4)        { src = Wq; dst = (__half2*)g_wqh; j = i - NX4; }
    else if (i < NX4 + NWQ4 + NWP4) { src = Wp; dst = (__half2*)g_pwh; j = i - NX4 - NWQ4; }
    else return;
    float4 v = __ldg(src + j);
    dst[2 * j]     = __floats2half2_rn(v.x, v.y);
    dst[2 * j + 1] = __floats2half2_rn(v.z, v.w);
}

// ---------------------------------------------------------------------------
// HMMA GEMM: 128x128 tile, 8 warps (32x64 each), K-chunk 32.
// 4-stage cp.async ring with copies issued 3 iterations ahead (wait_group 2),
// single fragment set (NO register double-buffer), one barrier per iteration.
// Stage s: A at s*20480, B at s*20480+10240.  Dyn smem 81920.
// ---------------------------------------------------------------------------
#define G_STAGE 20480
#define G_SMEM  81920

__global__ __launch_bounds__(256) void hgemm(const float* __restrict__ bias,
                                             float* __restrict__ out32,
                                             int mode)
{
    extern __shared__ __align__(16) char dsm[];

    const __half* Aptr = mode ? g_oh  : g_xh;
    const __half* Bptr = mode ? g_pwh : g_wqh;

    const int tid = threadIdx.x, lane = tid & 31, w = tid >> 5;
    const int wm = w >> 1, wn = w & 1;
    const int m0 = blockIdx.y * 128, n0 = blockIdx.x * 128;

    float acc[2][8][4];
#pragma unroll
    for (int mt = 0; mt < 2; mt++)
#pragma unroll
        for (int nt = 0; nt < 8; nt++)
#pragma unroll
            for (int c = 0; c < 4; c++) acc[mt][nt][c] = 0.f;

    const int a_row  = wm * 32 + (lane & 15);
    const int a_colh = (lane >> 4) * 8;
    const int b_row  = wn * 64 + (lane & 7) + ((lane >> 4) << 3);
    const int b_colh = ((lane >> 3) & 1) * 8;
    const int cr = tid >> 2, cc = (tid & 3) * 8;

    auto docopy = [&](int kc, int s) {
        char* Ab = dsm + s * G_STAGE;
        char* Bb = Ab + 10240;
#pragma unroll
        for (int i = 0; i < 2; i++) {
            int r = cr + i * 64;
            cp16(Ab + r * 80 + cc * 2, Aptr + (size_t)(m0 + r) * CH + kc * 32 + cc);
            cp16(Bb + r * 80 + cc * 2, Bptr + (size_t)(n0 + r) * CH + kc * 32 + cc);
        }
    };

    docopy(0, 0); CP_COMMIT();
    docopy(1, 1); CP_COMMIT();
    docopy(2, 2); CP_COMMIT();

    for (int kc = 0; kc < 16; kc++) {
        if (kc <= 13)      { CP_WAIT2(); }
        else if (kc == 14) { CP_WAIT1(); }
        else               { CP_WAIT0(); }
        __syncthreads();
        if (kc + 3 < 16) { docopy(kc + 3, (kc + 3) & 3); CP_COMMIT(); }

        char* Ab = dsm + (kc & 3) * G_STAGE;
        char* Bb = Ab + 10240;
#pragma unroll
        for (int ks = 0; ks < 2; ks++) {
            uint32_t aF[2][4];
#pragma unroll
            for (int mt = 0; mt < 2; mt++)
                ldm_x4(aF[mt], smem_u32(Ab + (a_row + mt * 16) * 80
                                           + (ks * 16 + a_colh) * 2));
            uint32_t bF[8][2];
#pragma unroll
            for (int q = 0; q < 4; q++) {
                uint32_t r[4];
                ldm_x4(r, smem_u32(Bb + (b_row + q * 16) * 80
                                      + (ks * 16 + b_colh) * 2));
                bF[2 * q][0] = r[0]; bF[2 * q][1] = r[1];
                bF[2 * q + 1][0] = r[2]; bF[2 * q + 1][1] = r[3];
            }
#pragma unroll
            for (int mt = 0; mt < 2; mt++)
#pragma unroll
                for (int nt = 0; nt < 8; nt++)
                    mma16816(acc[mt][nt], aF[mt], bF[nt]);
        }
    }

    const int qr = lane >> 2, qc = (lane & 3) * 2;
    if (mode == 0) {
#pragma unroll
        for (int mt = 0; mt < 2; mt++) {
#pragma unroll
            for (int nt = 0; nt < 8; nt++) {
                int jj = n0 + wn * 64 + nt * 8 + qc;
                float b0 = __ldg(&bias[jj]), b1 = __ldg(&bias[jj + 1]);
                int which = jj >> 9, h = (jj >> 5) & 15, dd = jj & 31;
#pragma unroll
                for (int rr = 0; rr < 2; rr++) {
                    int m = m0 + wm * 32 + mt * 16 + qr + rr * 8;
                    int b = m >> 10, n = m & 1023;
                    float v0 = acc[mt][nt][rr * 2 + 0] + b0;
                    float v1 = acc[mt][nt][rr * 2 + 1] + b1;
                    if (which == 0) { v0 *= QSC; v1 *= QSC; }
                    __half2 hv = __floats2half2_rn(v0, v1);
                    size_t off = ((size_t)(b * NHEAD + h) * NTOK + n) * HD + dd;
                    if (which == 0)      *(__half2*)&g_q[off] = hv;
                    else if (which == 1) *(__half2*)&g_k[off] = hv;
                    else                 *(__half2*)&g_v[off] = hv;
                }
            }
        }
    } else {
#pragma unroll
        for (int mt = 0; mt < 2; mt++) {
#pragma unroll
            for (int nt = 0; nt < 8; nt++) {
                int jj = n0 + wn * 64 + nt * 8 + qc;
                float b0 = __ldg(&bias[jj]), b1 = __ldg(&bias[jj + 1]);
#pragma unroll
                for (int rr = 0; rr < 2; rr++) {
                    int m = m0 + wm * 32 + mt * 16 + qr + rr * 8;
                    float2 v = make_float2(acc[mt][nt][rr * 2 + 0] + b0,
                                           acc[mt][nt][rr * 2 + 1] + b1);
                    *(float2*)&out32[(size_t)m * CH + jj] = v;
                }
            }
        }
    }
}

// ---------------------------------------------------------------------------
// Kernel 2: attention.  Round-8 structure, but l computed on the SCALAR pipes
// (float unpack of fp16 p + FADD) instead of the ones-column MMA: -11% tensor
// work on the bound pipe, free on the idle fma/alu pipes.
// ---------------------------------------------------------------------------
#define AT_QS   0
#define AT_KS   10240
#define AT_VS   25600
#define AT_RPB  40960
#define AT_SMEM 56960

__global__ __launch_bounds__(256) void attn_kernel(const float* __restrict__ rpb)
{
    extern __shared__ __align__(16) char dsm[];
    __half* Qs    = (__half*)(dsm + AT_QS);
    float*  rpb_s = (float*)(dsm + AT_RPB);

    const int bh = blockIdx.x;
    const int b  = bh >> 4, h = bh & 15;
    const int qbase = blockIdx.y * 128;
    const int tid = threadIdx.x, lane = tid & 31, w = tid >> 5;

    const int cr = tid >> 2, cc = (tid & 3) * 8;
    const __half* kbase = g_k + (size_t)bh * NTOK * HD;
    const __half* vbase = g_v + (size_t)bh * NTOK * HD;

    auto copy_kv = [&](int kt, int s) {
        char* Kb = dsm + AT_KS + s * 5120;
        char* Vb = dsm + AT_VS + s * 5120;
        cp16(Kb + cr * 80 + cc * 2, kbase + (size_t)(kt * 64 + cr) * HD + cc);
        cp16(Vb + cr * 80 + cc * 2, vbase + (size_t)(kt * 64 + cr) * HD + cc);
    };

    copy_kv(0, 0); CP_COMMIT();
    copy_kv(1, 1); CP_COMMIT();

    for (int e = tid; e < 3969; e += 256)
        rpb_s[e] = __ldg(rpb + (size_t)h * 3969 + e) * LOG2E;

    const __half* qg = g_q + ((size_t)bh * NTOK + qbase) * HD;
#pragma unroll
    for (int i = 0; i < 2; i++) {
        int e = tid + i * 256;
        int row = e >> 2, c8 = (e & 3) * 8;
        *(uint4*)(Qs + row * 40 + c8) = *(const uint4*)(qg + row * HD + c8);
    }
    __syncthreads();

    uint32_t aQ[2][4];
#pragma unroll
    for (int ks = 0; ks < 2; ks++)
        ldm_x4(aQ[ks], smem_u32(Qs + (w * 16 + (lane & 15)) * 40
                                   + ks * 16 + (lane >> 4) * 8));

    const int qr = lane >> 2, qc = (lane & 3) * 2;
    const int i1 = qbase + w * 16 + qr, i2 = i1 + 8;
    const int off1 = (31 - (i1 >> 5)) * 63 + (31 - (i1 & 31));
    const int off2 = (31 - (i2 >> 5)) * 63 + (31 - (i2 & 31));

    float l1 = 0.f, l2 = 0.f;
    float oacc[4][4];
#pragma unroll
    for (int i = 0; i < 4; i++)
#pragma unroll
        for (int c = 0; c < 4; c++) oacc[i][c] = 0.f;

    const int kb_row = (lane & 7) + ((lane >> 4) << 3);
    const int kb_col = ((lane >> 3) & 1) * 8;

    for (int kt = 0; kt < 16; kt++) {
        if (kt < 15) { CP_WAIT1(); } else { CP_WAIT0(); }
        __syncthreads();
        if (kt + 2 < 16) { copy_kv(kt + 2, (kt + 2) % 3); CP_COMMIT(); }

        const int s = kt % 3;
        char* Kb = dsm + AT_KS + s * 5120;
        char* Vb = dsm + AT_VS + s * 5120;

        float sc[8][4];
#pragma unroll
        for (int nt = 0; nt < 8; nt++) {
            int j0 = kt * 64 + nt * 8 + qc;
            int ja = j0 + 31 * (j0 >> 5);
            sc[nt][0] = rpb_s[off1 + ja];
            sc[nt][1] = rpb_s[off1 + ja + 1];
            sc[nt][2] = rpb_s[off2 + ja];
            sc[nt][3] = rpb_s[off2 + ja + 1];
        }

#pragma unroll
        for (int ks = 0; ks < 2; ks++) {
#pragma unroll
            for (int q = 0; q < 4; q++) {
                uint32_t r[4];
                ldm_x4(r, smem_u32(Kb + (q * 16 + kb_row) * 80
                                      + (ks * 16 + kb_col) * 2));
                uint32_t b0[2] = { r[0], r[1] }, b1[2] = { r[2], r[3] };
                mma16816(sc[2 * q],     aQ[ks], b0);
                mma16816(sc[2 * q + 1], aQ[ks], b1);
            }
        }

        uint32_t pexp[8][2];
#pragma unroll
        for (int nt = 0; nt < 8; nt++) {
            __half2 e0 = h2exp2(__floats2half2_rn(sc[nt][0], sc[nt][1]));
            __half2 e1 = h2exp2(__floats2half2_rn(sc[nt][2], sc[nt][3]));
            pexp[nt][0] = *(uint32_t*)&e0;
            pexp[nt][1] = *(uint32_t*)&e1;
            float2 f0 = __half22float2(e0);
            float2 f1 = __half22float2(e1);
            l1 += f0.x + f0.y;
            l2 += f1.x + f1.y;
        }

#pragma unroll
        for (int kk = 0; kk < 4; kk++) {
            uint32_t aP[4] = { pexp[2 * kk][0], pexp[2 * kk][1],
                               pexp[2 * kk + 1][0], pexp[2 * kk + 1][1] };
#pragma unroll
            for (int dp = 0; dp < 2; dp++) {
                uint32_t r[4];
                ldm_x4_t(r, smem_u32(Vb + (kk * 16 + (lane & 15)) * 80
                                        + (dp * 16 + (lane >> 4) * 8) * 2));
                uint32_t b0[2] = { r[0], r[1] }, b1[2] = { r[2], r[3] };
                mma16816(oacc[2 * dp],     aP, b0);
                mma16816(oacc[2 * dp + 1], aP, b1);
            }
        }
    }

    l1 += __shfl_xor_sync(0xffffffffu, l1, 1);
    l1 += __shfl_xor_sync(0xffffffffu, l1, 2);
    l2 += __shfl_xor_sync(0xffffffffu, l2, 1);
    l2 += __shfl_xor_sync(0xffffffffu, l2, 2);

    float inv1 = 1.f / l1, inv2 = 1.f / l2;
#pragma unroll
    for (int ntd = 0; ntd < 4; ntd++) {
        int d0 = ntd * 8 + qc;
        *(__half2*)&g_oh[((size_t)b * NTOK + i1) * CH + h * HD + d0] =
            __floats2half2_rn(oacc[ntd][0] * inv1, oacc[ntd][1] * inv1);
        *(__half2*)&g_oh[((size_t)b * NTOK + i2) * CH + h * HD + d0] =
            __floats2half2_rn(oacc[ntd][2] * inv2, oacc[ntd][3] * inv2);
    }
}

// ---------------------------------------------------------------------------
extern "C" void kernel_launch(void* const* d_in, const int* in_sizes, int n_in,
                              void* d_out, int out_size)
{
    const float* x      = (const float*)d_in[0];
    const float* qkv_w  = (const float*)d_in[1];
    const float* qkv_b  = (const float*)d_in[2];
    const float* rpb    = (const float*)d_in[3];
    const float* proj_w = (const float*)d_in[4];
    const float* proj_b = (const float*)d_in[5];
    float* out = (float*)d_out;

    cudaFuncSetAttribute(hgemm, cudaFuncAttributeMaxDynamicSharedMemorySize, G_SMEM);
    cudaFuncSetAttribute(attn_kernel, cudaFuncAttributeMaxDynamicSharedMemorySize, AT_SMEM);

    convert_all<<<(NX4 + NWQ4 + NWP4 + 255) / 256, 256>>>(
        (const float4*)x, (const float4*)qkv_w, (const float4*)proj_w);
    hgemm<<<dim3(12, 64), 256, G_SMEM>>>(qkv_b, nullptr, 0);
    attn_kernel<<<dim3(BATCH * NHEAD, NTOK / 128), 256, AT_SMEM>>>(rpb);
    hgemm<<<dim3(4, 64), 256, G_SMEM>>>(proj_b, out, 1);
}

// round 15
// speedup vs baseline: 1.8071x; 1.0355x over previous
#include <cuda_runtime.h>
#include <cuda_fp16.h>
#include <cstdint>

#define BATCH 8
#define NTOK  1024
#define CH    512
#define NHEAD 16
#define HD    32
#define LOG2E 1.4426950408889634f
// q is pre-scaled by SCALE*log2e so QK^T lands in the 2^x domain
#define QSC (0.17677669529663689f * 1.4426950408889634f)

// fp16 scratch
__device__ __half g_xh[BATCH * NTOK * CH];
__device__ __half g_wqh[3 * CH * CH];
__device__ __half g_pwh[CH * CH];
__device__ __half g_q[BATCH * NHEAD * NTOK * HD];
__device__ __half g_k[BATCH * NHEAD * NTOK * HD];
__device__ __half g_v[BATCH * NHEAD * NTOK * HD];
__device__ __half g_oh[BATCH * NTOK * CH];

__device__ __forceinline__ uint32_t smem_u32(const void* p) {
    return (uint32_t)__cvta_generic_to_shared(p);
}
__device__ __forceinline__ void cp16(void* sdst, const void* gsrc) {
    asm volatile("cp.async.cg.shared.global [%0], [%1], 16;"
                 :: "r"(smem_u32(sdst)), "l"(gsrc));
}
#define CP_COMMIT() asm volatile("cp.async.commit_group;" ::: "memory")
#define CP_WAIT0()  asm volatile("cp.async.wait_group 0;" ::: "memory")
#define CP_WAIT1()  asm volatile("cp.async.wait_group 1;" ::: "memory")

__device__ __forceinline__ void ldm_x4(uint32_t* r, uint32_t a) {
    asm volatile("ldmatrix.sync.aligned.m8n8.x4.shared.b16 {%0,%1,%2,%3}, [%4];"
                 : "=r"(r[0]), "=r"(r[1]), "=r"(r[2]), "=r"(r[3]) : "r"(a));
}
__device__ __forceinline__ void ldm_x4_t(uint32_t* r, uint32_t a) {
    asm volatile("ldmatrix.sync.aligned.m8n8.x4.trans.shared.b16 {%0,%1,%2,%3}, [%4];"
                 : "=r"(r[0]), "=r"(r[1]), "=r"(r[2]), "=r"(r[3]) : "r"(a));
}
__device__ __forceinline__ void mma16816(float* c, const uint32_t* a, const uint32_t* b) {
    asm volatile(
        "mma.sync.aligned.m16n8k16.row.col.f32.f16.f16.f32 "
        "{%0,%1,%2,%3}, {%4,%5,%6,%7}, {%8,%9}, {%0,%1,%2,%3};"
        : "+f"(c[0]), "+f"(c[1]), "+f"(c[2]), "+f"(c[3])
        : "r"(a[0]), "r"(a[1]), "r"(a[2]), "r"(a[3]), "r"(b[0]), "r"(b[1]));
}

// ---------------------------------------------------------------------------
// Kernel 0: fp32 -> fp16 conversion of X, qkv_w, proj_w.
// ---------------------------------------------------------------------------
#define NX4  (BATCH * NTOK * CH / 4)
#define NWQ4 (3 * CH * CH / 4)
#define NWP4 (CH * CH / 4)

__global__ __launch_bounds__(256) void convert_all(const float4* __restrict__ X,
                                                   const float4* __restrict__ Wq,
                                                   const float4* __restrict__ Wp)
{
    int i = blockIdx.x * 256 + threadIdx.x;
    const float4* src;
    __half2* dst;
    int j;
    if (i < NX4)                    { src = X;  dst = (__half2*)g_xh;  j = i; }
    else if (i < NX4 + NWQ4)        { src = Wq; dst = (__half2*)g_wqh; j = i - NX4; }
    else if (i < NX4 + NWQ4 + NWP4) { src = Wp; dst = (__half2*)g_pwh; j = i - NX4 - NWQ4; }
    else return;
    float4 v = __ldg(src + j);
    dst[2 * j]     = __floats2half2_rn(v.x, v.y);
    dst[2 * j + 1] = __floats2half2_rn(v.z, v.w);
}

// ---------------------------------------------------------------------------
// HMMA GEMM: 128x128 tile, 8 warps (32x64 each), K-chunk 32, 3-stage cp.async
// ring with ONE __syncthreads per K-iteration.  (Best measured configuration.)
// ---------------------------------------------------------------------------
#define GA_STAGE 10240
#define GB_BASE  30720
#define G_SMEM   61440

__global__ __launch_bounds__(256) void hgemm(const float* __restrict__ bias,
                                             float* __restrict__ out32,
                                             int mode)
{
    extern __shared__ __align__(16) char dsm[];

    const __half* Aptr = mode ? g_oh  : g_xh;
    const __half* Bptr = mode ? g_pwh : g_wqh;

    const int tid = threadIdx.x, lane = tid & 31, w = tid >> 5;
    const int wm = w >> 1, wn = w & 1;
    const int m0 = blockIdx.y * 128, n0 = blockIdx.x * 128;

    float acc[2][8][4];
#pragma unroll
    for (int mt = 0; mt < 2; mt++)
#pragma unroll
        for (int nt = 0; nt < 8; nt++)
#pragma unroll
            for (int c = 0; c < 4; c++) acc[mt][nt][c] = 0.f;

    const int a_row  = wm * 32 + (lane & 15);
    const int a_colh = (lane >> 4) * 8;
    const int b_row  = wn * 64 + (lane & 7) + ((lane >> 4) << 3);
    const int b_colh = ((lane >> 3) & 1) * 8;

    const int cr = tid >> 2, cc = (tid & 3) * 8;

    auto docopy = [&](int kc, int s) {
        char* Ab = dsm + s * GA_STAGE;
        char* Bb = dsm + GB_BASE + s * GA_STAGE;
#pragma unroll
        for (int i = 0; i < 2; i++) {
            int r = cr + i * 64;
            cp16(Ab + r * 80 + cc * 2, Aptr + (size_t)(m0 + r) * CH + kc * 32 + cc);
            cp16(Bb + r * 80 + cc * 2, Bptr + (size_t)(n0 + r) * CH + kc * 32 + cc);
        }
    };

    docopy(0, 0); CP_COMMIT();
    docopy(1, 1); CP_COMMIT();

    for (int kc = 0; kc < 16; kc++) {
        if (kc < 15) { CP_WAIT1(); } else { CP_WAIT0(); }
        __syncthreads();
        if (kc + 2 < 16) { docopy(kc + 2, (kc + 2) % 3); CP_COMMIT(); }

        const int s = kc % 3;
        char* Ab = dsm + s * GA_STAGE;
        char* Bb = dsm + GB_BASE + s * GA_STAGE;
#pragma unroll
        for (int ks = 0; ks < 2; ks++) {
            uint32_t aF[2][4];
#pragma unroll
            for (int mt = 0; mt < 2; mt++)
                ldm_x4(aF[mt], smem_u32(Ab + (a_row + mt * 16) * 80
                                           + (ks * 16 + a_colh) * 2));
            uint32_t bF[8][2];
#pragma unroll
            for (int q = 0; q < 4; q++) {
                uint32_t r[4];
                ldm_x4(r, smem_u32(Bb + (b_row + q * 16) * 80
                                      + (ks * 16 + b_colh) * 2));
                bF[2 * q][0] = r[0]; bF[2 * q][1] = r[1];
                bF[2 * q + 1][0] = r[2]; bF[2 * q + 1][1] = r[3];
            }
#pragma unroll
            for (int mt = 0; mt < 2; mt++)
#pragma unroll
                for (int nt = 0; nt < 8; nt++)
                    mma16816(acc[mt][nt], aF[mt], bF[nt]);
        }
    }

    const int qr = lane >> 2, qc = (lane & 3) * 2;
    if (mode == 0) {
#pragma unroll
        for (int mt = 0; mt < 2; mt++) {
#pragma unroll
            for (int nt = 0; nt < 8; nt++) {
                int jj = n0 + wn * 64 + nt * 8 + qc;
                float b0 = __ldg(&bias[jj]), b1 = __ldg(&bias[jj + 1]);
                int which = jj >> 9, h = (jj >> 5) & 15, dd = jj & 31;
#pragma unroll
                for (int rr = 0; rr < 2; rr++) {
                    int m = m0 + wm * 32 + mt * 16 + qr + rr * 8;
                    int b = m >> 10, n = m & 1023;
                    float v0 = acc[mt][nt][rr * 2 + 0] + b0;
                    float v1 = acc[mt][nt][rr * 2 + 1] + b1;
                    if (which == 0) { v0 *= QSC; v1 *= QSC; }   // fold log2e into q
                    __half2 hv = __floats2half2_rn(v0, v1);
                    size_t off = ((size_t)(b * NHEAD + h) * NTOK + n) * HD + dd;
                    if (which == 0)      *(__half2*)&g_q[off] = hv;
                    else if (which == 1) *(__half2*)&g_k[off] = hv;
                    else                 *(__half2*)&g_v[off] = hv;
                }
            }
        }
    } else {
#pragma unroll
        for (int mt = 0; mt < 2; mt++) {
#pragma unroll
            for (int nt = 0; nt < 8; nt++) {
                int jj = n0 + wn * 64 + nt * 8 + qc;
                float b0 = __ldg(&bias[jj]), b1 = __ldg(&bias[jj + 1]);
#pragma unroll
                for (int rr = 0; rr < 2; rr++) {
                    int m = m0 + wm * 32 + mt * 16 + qr + rr * 8;
                    float2 v = make_float2(acc[mt][nt][rr * 2 + 0] + b0,
                                           acc[mt][nt][rr * 2 + 1] + b1);
                    *(float2*)&out32[(size_t)m * CH + jj] = v;
                }
            }
        }
    }
}

// ---------------------------------------------------------------------------
// Kernel 2: attention, 8 warps / 128 queries per block, 3-stage cp.async
// K/V ring.  Softmax in the log2/fp16 domain:
//   - RPB bias (pre-scaled by log2e) is the accumulator INIT for QK^T
//   - p = h2exp2(half2(t)) -- fp16 MUFU, feeds PV A-fragments directly
//   - l = P @ ones-column accumulated by an extra n8 MMA (off critical path)
// ---------------------------------------------------------------------------
#define AT_QS   0
#define AT_KS   10240
#define AT_VS   25600
#define AT_RPB  40960
#define AT_SMEM 56960

__global__ __launch_bounds__(256) void attn_kernel(const float* __restrict__ rpb)
{
    extern __shared__ __align__(16) char dsm[];
    __half* Qs    = (__half*)(dsm + AT_QS);
    float*  rpb_s = (float*)(dsm + AT_RPB);

    const int bh = blockIdx.x;
    const int b  = bh >> 4, h = bh & 15;
    const int qbase = blockIdx.y * 128;
    const int tid = threadIdx.x, lane = tid & 31, w = tid >> 5;

    const int cr = tid >> 2, cc = (tid & 3) * 8;
    const __half* kbase = g_k + (size_t)bh * NTOK * HD;
    const __half* vbase = g_v + (size_t)bh * NTOK * HD;

    auto copy_kv = [&](int kt, int s) {
        char* Kb = dsm + AT_KS + s * 5120;
        char* Vb = dsm + AT_VS + s * 5120;
        cp16(Kb + cr * 80 + cc * 2, kbase + (size_t)(kt * 64 + cr) * HD + cc);
        cp16(Vb + cr * 80 + cc * 2, vbase + (size_t)(kt * 64 + cr) * HD + cc);
    };

    copy_kv(0, 0); CP_COMMIT();
    copy_kv(1, 1); CP_COMMIT();

    // bias pre-scaled by log2e so exp becomes pure 2^x
    for (int e = tid; e < 3969; e += 256)
        rpb_s[e] = __ldg(rpb + (size_t)h * 3969 + e) * LOG2E;

    const __half* qg = g_q + ((size_t)bh * NTOK + qbase) * HD;
#pragma unroll
    for (int i = 0; i < 2; i++) {
        int e = tid + i * 256;
        int row = e >> 2, c8 = (e & 3) * 8;
        *(uint4*)(Qs + row * 40 + c8) = *(const uint4*)(qg + row * HD + c8);
    }
    __syncthreads();

    uint32_t aQ[2][4];
#pragma unroll
    for (int ks = 0; ks < 2; ks++)
        ldm_x4(aQ[ks], smem_u32(Qs + (w * 16 + (lane & 15)) * 40
                                   + ks * 16 + (lane >> 4) * 8));

    const int qr = lane >> 2, qc = (lane & 3) * 2;
    const int i1 = qbase + w * 16 + qr, i2 = i1 + 8;
    const int off1 = (31 - (i1 >> 5)) * 63 + (31 - (i1 & 31));
    const int off2 = (31 - (i2 >> 5)) * 63 + (31 - (i2 & 31));

    float oacc[4][4];
    float lacc[4];
#pragma unroll
    for (int i = 0; i < 4; i++) {
        lacc[i] = 0.f;
#pragma unroll
        for (int c = 0; c < 4; c++) oacc[i][c] = 0.f;
    }

    // ones-column B fragment: col 0 of an n8 tile = 1.0 for all k
    uint32_t bones[2];
    bones[0] = bones[1] = (lane < 4) ? 0x3C003C00u : 0u;

    const int kb_row = (lane & 7) + ((lane >> 4) << 3);
    const int kb_col = ((lane >> 3) & 1) * 8;

    for (int kt = 0; kt < 16; kt++) {
        if (kt < 15) { CP_WAIT1(); } else { CP_WAIT0(); }
        __syncthreads();
        if (kt + 2 < 16) { copy_kv(kt + 2, (kt + 2) % 3); CP_COMMIT(); }

        const int s = kt % 3;
        char* Kb = dsm + AT_KS + s * 5120;
        char* Vb = dsm + AT_VS + s * 5120;

        // accumulator INIT = bias (log2-domain)
        float sc[8][4];
#pragma unroll
        for (int nt = 0; nt < 8; nt++) {
            int j0 = kt * 64 + nt * 8 + qc;
            int ja = j0 + 31 * (j0 >> 5);
            sc[nt][0] = rpb_s[off1 + ja];
            sc[nt][1] = rpb_s[off1 + ja + 1];
            sc[nt][2] = rpb_s[off2 + ja];
            sc[nt][3] = rpb_s[off2 + ja + 1];
        }

#pragma unroll
        for (int ks = 0; ks < 2; ks++) {
#pragma unroll
            for (int q = 0; q < 4; q++) {
                uint32_t r[4];
                ldm_x4(r, smem_u32(Kb + (q * 16 + kb_row) * 80
                                      + (ks * 16 + kb_col) * 2));
                uint32_t b0[2] = { r[0], r[1] }, b1[2] = { r[2], r[3] };
                mma16816(sc[2 * q],     aQ[ks], b0);
                mma16816(sc[2 * q + 1], aQ[ks], b1);
            }
        }

        // p = 2^t in fp16 (f16x2 MUFU), straight into A-fragments
        uint32_t pexp[8][2];
#pragma unroll
        for (int nt = 0; nt < 8; nt++) {
            __half2 e0 = h2exp2(__floats2half2_rn(sc[nt][0], sc[nt][1]));
            __half2 e1 = h2exp2(__floats2half2_rn(sc[nt][2], sc[nt][3]));
            pexp[nt][0] = *(uint32_t*)&e0;
            pexp[nt][1] = *(uint32_t*)&e1;
        }

        // P @ [V | 1]
#pragma unroll
        for (int kk = 0; kk < 4; kk++) {
            uint32_t aP[4] = { pexp[2 * kk][0], pexp[2 * kk][1],
                               pexp[2 * kk + 1][0], pexp[2 * kk + 1][1] };
#pragma unroll
            for (int dp = 0; dp < 2; dp++) {
                uint32_t r[4];
                ldm_x4_t(r, smem_u32(Vb + (kk * 16 + (lane & 15)) * 80
                                        + (dp * 16 + (lane >> 4) * 8) * 2));
                uint32_t b0[2] = { r[0], r[1] }, b1[2] = { r[2], r[3] };
                mma16816(oacc[2 * dp],     aP, b0);
                mma16816(oacc[2 * dp + 1], aP, b1);
            }
            mma16816(lacc, aP, bones);   // row-sum column
        }
    }

    // l lives in col 0 of the lacc tile -> lanes with lane%4==0; broadcast in quad
    float l1 = __shfl_sync(0xffffffffu, lacc[0], lane & ~3);
    float l2 = __shfl_sync(0xffffffffu, lacc[2], lane & ~3);

    float inv1 = 1.f / l1, inv2 = 1.f / l2;
#pragma unroll
    for (int ntd = 0; ntd < 4; ntd++) {
        int d0 = ntd * 8 + qc;
        *(__half2*)&g_oh[((size_t)b * NTOK + i1) * CH + h * HD + d0] =
            __floats2half2_rn(oacc[ntd][0] * inv1, oacc[ntd][1] * inv1);
        *(__half2*)&g_oh[((size_t)b * NTOK + i2) * CH + h * HD + d0] =
            __floats2half2_rn(oacc[ntd][2] * inv2, oacc[ntd][3] * inv2);
    }
}

// ---------------------------------------------------------------------------
extern "C" void kernel_launch(void* const* d_in, const int* in_sizes, int n_in,
                              void* d_out, int out_size)
{
    const float* x      = (const float*)d_in[0];
    const float* qkv_w  = (const float*)d_in[1];
    const float* qkv_b  = (const float*)d_in[2];
    const float* rpb    = (const float*)d_in[3];
    const float* proj_w = (const float*)d_in[4];
    const float* proj_b = (const float*)d_in[5];
    float* out = (float*)d_out;

    cudaFuncSetAttribute(hgemm, cudaFuncAttributeMaxDynamicSharedMemorySize, G_SMEM);
    cudaFuncSetAttribute(attn_kernel, cudaFuncAttributeMaxDynamicSharedMemorySize, AT_SMEM);

    convert_all<<<(NX4 + NWQ4 + NWP4 + 255) / 256, 256>>>(
        (const float4*)x, (const float4*)qkv_w, (const float4*)proj_w);
    hgemm<<<dim3(12, 64), 256, G_SMEM>>>(qkv_b, nullptr, 0);
    attn_kernel<<<dim3(BATCH * NHEAD, NTOK / 128), 256, AT_SMEM>>>(rpb);
    hgemm<<<dim3(4, 64), 256, G_SMEM>>>(proj_b, out, 1);
}

// round 16
// speedup vs baseline: 1.8587x; 1.0285x over previous
#include <cuda_runtime.h>
#include <cuda_fp16.h>
#include <cstdint>

#define BATCH 8
#define NTOK  1024
#define CH    512
#define NHEAD 16
#define HD    32
#define LOG2E 1.4426950408889634f
// q is pre-scaled by SCALE*log2e so QK^T lands in the 2^x domain
#define QSC (0.17677669529663689f * 1.4426950408889634f)

// fp16 scratch
__device__ __half g_xh[BATCH * NTOK * CH];
__device__ __half g_wqh[3 * CH * CH];
__device__ __half g_pwh[CH * CH];
__device__ __half g_q[BATCH * NHEAD * NTOK * HD];
__device__ __half g_k[BATCH * NHEAD * NTOK * HD];
__device__ __half g_v[BATCH * NHEAD * NTOK * HD];
__device__ __half g_oh[BATCH * NTOK * CH];

__device__ __forceinline__ uint32_t smem_u32(const void* p) {
    return (uint32_t)__cvta_generic_to_shared(p);
}
__device__ __forceinline__ void cp16(void* sdst, const void* gsrc) {
    asm volatile("cp.async.cg.shared.global [%0], [%1], 16;"
                 :: "r"(smem_u32(sdst)), "l"(gsrc));
}
#define CP_COMMIT() asm volatile("cp.async.commit_group;" ::: "memory")
#define CP_WAIT0()  asm volatile("cp.async.wait_group 0;" ::: "memory")
#define CP_WAIT1()  asm volatile("cp.async.wait_group 1;" ::: "memory")

__device__ __forceinline__ void ldm_x4(uint32_t* r, uint32_t a) {
    asm volatile("ldmatrix.sync.aligned.m8n8.x4.shared.b16 {%0,%1,%2,%3}, [%4];"
                 : "=r"(r[0]), "=r"(r[1]), "=r"(r[2]), "=r"(r[3]) : "r"(a));
}
__device__ __forceinline__ void ldm_x4_t(uint32_t* r, uint32_t a) {
    asm volatile("ldmatrix.sync.aligned.m8n8.x4.trans.shared.b16 {%0,%1,%2,%3}, [%4];"
                 : "=r"(r[0]), "=r"(r[1]), "=r"(r[2]), "=r"(r[3]) : "r"(a));
}
__device__ __forceinline__ void mma16816(float* c, const uint32_t* a, const uint32_t* b) {
    asm volatile(
        "mma.sync.aligned.m16n8k16.row.col.f32.f16.f16.f32 "
        "{%0,%1,%2,%3}, {%4,%5,%6,%7}, {%8,%9}, {%0,%1,%2,%3};"
        : "+f"(c[0]), "+f"(c[1]), "+f"(c[2]), "+f"(c[3])
        : "r"(a[0]), "r"(a[1]), "r"(a[2]), "r"(a[3]), "r"(b[0]), "r"(b[1]));
}
// fp16-accumulated variant: C = 2 packed half2 regs, layout == PV A-fragment
__device__ __forceinline__ void mma16816_h(uint32_t* c, const uint32_t* a, const uint32_t* b) {
    asm volatile(
        "mma.sync.aligned.m16n8k16.row.col.f16.f16.f16.f16 "
        "{%0,%1}, {%2,%3,%4,%5}, {%6,%7}, {%0,%1};"
        : "+r"(c[0]), "+r"(c[1])
        : "r"(a[0]), "r"(a[1]), "r"(a[2]), "r"(a[3]), "r"(b[0]), "r"(b[1]));
}
__device__ __forceinline__ uint32_t pack_h2(float x, float y) {
    __half2 h = __floats2half2_rn(x, y);
    return *(uint32_t*)&h;
}

// ---------------------------------------------------------------------------
// Kernel 0: fp32 -> fp16 conversion of X, qkv_w, proj_w.
// ---------------------------------------------------------------------------
#define NX4  (BATCH * NTOK * CH / 4)
#define NWQ4 (3 * CH * CH / 4)
#define NWP4 (CH * CH / 4)

__global__ __launch_bounds__(256) void convert_all(const float4* __restrict__ X,
                                                   const float4* __restrict__ Wq,
                                                   const float4* __restrict__ Wp)
{
    int i = blockIdx.x * 256 + threadIdx.x;
    const float4* src;
    __half2* dst;
    int j;
    if (i < NX4)                    { src = X;  dst = (__half2*)g_xh;  j = i; }
    else if (i < NX4 + NWQ4)        { src = Wq; dst = (__half2*)g_wqh; j = i - NX4; }
    else if (i < NX4 + NWQ4 + NWP4) { src = Wp; dst = (__half2*)g_pwh; j = i - NX4 - NWQ4; }
    else return;
    float4 v = __ldg(src + j);
    dst[2 * j]     = __floats2half2_rn(v.x, v.y);
    dst[2 * j + 1] = __floats2half2_rn(v.z, v.w);
}

// ---------------------------------------------------------------------------
// HMMA GEMM: 128x128 tile, 8 warps (32x64 each), K-chunk 32, 3-stage cp.async
// ring with ONE __syncthreads per K-iteration.  (Best measured configuration.)
// ---------------------------------------------------------------------------
#define GA_STAGE 10240
#define GB_BASE  30720
#define G_SMEM   61440

__global__ __launch_bounds__(256) void hgemm(const float* __restrict__ bias,
                                             float* __restrict__ out32,
                                             int mode)
{
    extern __shared__ __align__(16) char dsm[];

    const __half* Aptr = mode ? g_oh  : g_xh;
    const __half* Bptr = mode ? g_pwh : g_wqh;

    const int tid = threadIdx.x, lane = tid & 31, w = tid >> 5;
    const int wm = w >> 1, wn = w & 1;
    const int m0 = blockIdx.y * 128, n0 = blockIdx.x * 128;

    float acc[2][8][4];
#pragma unroll
    for (int mt = 0; mt < 2; mt++)
#pragma unroll
        for (int nt = 0; nt < 8; nt++)
#pragma unroll
            for (int c = 0; c < 4; c++) acc[mt][nt][c] = 0.f;

    const int a_row  = wm * 32 + (lane & 15);
    const int a_colh = (lane >> 4) * 8;
    const int b_row  = wn * 64 + (lane & 7) + ((lane >> 4) << 3);
    const int b_colh = ((lane >> 3) & 1) * 8;

    const int cr = tid >> 2, cc = (tid & 3) * 8;

    auto docopy = [&](int kc, int s) {
        char* Ab = dsm + s * GA_STAGE;
        char* Bb = dsm + GB_BASE + s * GA_STAGE;
#pragma unroll
        for (int i = 0; i < 2; i++) {
            int r = cr + i * 64;
            cp16(Ab + r * 80 + cc * 2, Aptr + (size_t)(m0 + r) * CH + kc * 32 + cc);
            cp16(Bb + r * 80 + cc * 2, Bptr + (size_t)(n0 + r) * CH + kc * 32 + cc);
        }
    };

    docopy(0, 0); CP_COMMIT();
    docopy(1, 1); CP_COMMIT();

    for (int kc = 0; kc < 16; kc++) {
        if (kc < 15) { CP_WAIT1(); } else { CP_WAIT0(); }
        __syncthreads();
        if (kc + 2 < 16) { docopy(kc + 2, (kc + 2) % 3); CP_COMMIT(); }

        const int s = kc % 3;
        char* Ab = dsm + s * GA_STAGE;
        char* Bb = dsm + GB_BASE + s * GA_STAGE;
#pragma unroll
        for (int ks = 0; ks < 2; ks++) {
            uint32_t aF[2][4];
#pragma unroll
            for (int mt = 0; mt < 2; mt++)
                ldm_x4(aF[mt], smem_u32(Ab + (a_row + mt * 16) * 80
                                           + (ks * 16 + a_colh) * 2));
            uint32_t bF[8][2];
#pragma unroll
            for (int q = 0; q < 4; q++) {
                uint32_t r[4];
                ldm_x4(r, smem_u32(Bb + (b_row + q * 16) * 80
                                      + (ks * 16 + b_colh) * 2));
                bF[2 * q][0] = r[0]; bF[2 * q][1] = r[1];
                bF[2 * q + 1][0] = r[2]; bF[2 * q + 1][1] = r[3];
            }
#pragma unroll
            for (int mt = 0; mt < 2; mt++)
#pragma unroll
                for (int nt = 0; nt < 8; nt++)
                    mma16816(acc[mt][nt], aF[mt], bF[nt]);
        }
    }

    const int qr = lane >> 2, qc = (lane & 3) * 2;
    if (mode == 0) {
#pragma unroll
        for (int mt = 0; mt < 2; mt++) {
#pragma unroll
            for (int nt = 0; nt < 8; nt++) {
                int jj = n0 + wn * 64 + nt * 8 + qc;
                float b0 = __ldg(&bias[jj]), b1 = __ldg(&bias[jj + 1]);
                int which = jj >> 9, h = (jj >> 5) & 15, dd = jj & 31;
#pragma unroll
                for (int rr = 0; rr < 2; rr++) {
                    int m = m0 + wm * 32 + mt * 16 + qr + rr * 8;
                    int b = m >> 10, n = m & 1023;
                    float v0 = acc[mt][nt][rr * 2 + 0] + b0;
                    float v1 = acc[mt][nt][rr * 2 + 1] + b1;
                    if (which == 0) { v0 *= QSC; v1 *= QSC; }   // fold log2e into q
                    __half2 hv = __floats2half2_rn(v0, v1);
                    size_t off = ((size_t)(b * NHEAD + h) * NTOK + n) * HD + dd;
                    if (which == 0)      *(__half2*)&g_q[off] = hv;
                    else if (which == 1) *(__half2*)&g_k[off] = hv;
                    else                 *(__half2*)&g_v[off] = hv;
                }
            }
        }
    } else {
#pragma unroll
        for (int mt = 0; mt < 2; mt++) {
#pragma unroll
            for (int nt = 0; nt < 8; nt++) {
                int jj = n0 + wn * 64 + nt * 8 + qc;
                float b0 = __ldg(&bias[jj]), b1 = __ldg(&bias[jj + 1]);
#pragma unroll
                for (int rr = 0; rr < 2; rr++) {
                    int m = m0 + wm * 32 + mt * 16 + qr + rr * 8;
                    float2 v = make_float2(acc[mt][nt][rr * 2 + 0] + b0,
                                           acc[mt][nt][rr * 2 + 1] + b1);
                    *(float2*)&out32[(size_t)m * CH + jj] = v;
                }
            }
        }
    }
}

// ---------------------------------------------------------------------------
// Kernel 2: attention, 8 warps / 128 queries per block, 3-stage cp.async
// K/V ring.  Log2-domain softmax with fp16-accumulated QK^T:
//   - bias (log2e-scaled) packed to half2 C-init BEFORE the async wait
//   - QK mma f16.f16.f16.f16 -> C regs ARE the PV A-fragment layout
//   - p = h2exp2 directly on the MMA output register (no pack on critical path)
//   - l = P @ ones-column via extra n8 MMA (fp32 acc)
// ---------------------------------------------------------------------------
#define AT_QS   0
#define AT_KS   10240
#define AT_VS   25600
#define AT_RPB  40960
#define AT_SMEM 56960

__global__ __launch_bounds__(256) void attn_kernel(const float* __restrict__ rpb)
{
    extern __shared__ __align__(16) char dsm[];
    __half* Qs    = (__half*)(dsm + AT_QS);
    float*  rpb_s = (float*)(dsm + AT_RPB);

    const int bh = blockIdx.x;
    const int b  = bh >> 4, h = bh & 15;
    const int qbase = blockIdx.y * 128;
    const int tid = threadIdx.x, lane = tid & 31, w = tid >> 5;

    const int cr = tid >> 2, cc = (tid & 3) * 8;
    const __half* kbase = g_k + (size_t)bh * NTOK * HD;
    const __half* vbase = g_v + (size_t)bh * NTOK * HD;

    auto copy_kv = [&](int kt, int s) {
        char* Kb = dsm + AT_KS + s * 5120;
        char* Vb = dsm + AT_VS + s * 5120;
        cp16(Kb + cr * 80 + cc * 2, kbase + (size_t)(kt * 64 + cr) * HD + cc);
        cp16(Vb + cr * 80 + cc * 2, vbase + (size_t)(kt * 64 + cr) * HD + cc);
    };

    copy_kv(0, 0); CP_COMMIT();
    copy_kv(1, 1); CP_COMMIT();

    // bias pre-scaled by log2e so exp becomes pure 2^x
    for (int e = tid; e < 3969; e += 256)
        rpb_s[e] = __ldg(rpb + (size_t)h * 3969 + e) * LOG2E;

    const __half* qg = g_q + ((size_t)bh * NTOK + qbase) * HD;
#pragma unroll
    for (int i = 0; i < 2; i++) {
        int e = tid + i * 256;
        int row = e >> 2, c8 = (e & 3) * 8;
        *(uint4*)(Qs + row * 40 + c8) = *(const uint4*)(qg + row * HD + c8);
    }
    __syncthreads();

    uint32_t aQ[2][4];
#pragma unroll
    for (int ks = 0; ks < 2; ks++)
        ldm_x4(aQ[ks], smem_u32(Qs + (w * 16 + (lane & 15)) * 40
                                   + ks * 16 + (lane >> 4) * 8));

    const int qr = lane >> 2, qc = (lane & 3) * 2;
    const int i1 = qbase + w * 16 + qr, i2 = i1 + 8;
    const int off1 = (31 - (i1 >> 5)) * 63 + (31 - (i1 & 31));
    const int off2 = (31 - (i2 >> 5)) * 63 + (31 - (i2 & 31));

    float oacc[4][4];
    float lacc[4];
#pragma unroll
    for (int i = 0; i < 4; i++) {
        lacc[i] = 0.f;
#pragma unroll
        for (int c = 0; c < 4; c++) oacc[i][c] = 0.f;
    }

    // ones-column B fragment: col 0 of an n8 tile = 1.0 for all k
    uint32_t bones[2];
    bones[0] = bones[1] = (lane < 4) ? 0x3C003C00u : 0u;

    const int kb_row = (lane & 7) + ((lane >> 4) << 3);
    const int kb_col = ((lane >> 3) & 1) * 8;

    for (int kt = 0; kt < 16; kt++) {
        // ---- C-init (bias, half2-packed) BEFORE the wait: hides pack+LDS ----
        uint32_t sc2[8][2];
#pragma unroll
        for (int nt = 0; nt < 8; nt++) {
            int j0 = kt * 64 + nt * 8 + qc;
            int ja = j0 + 31 * (j0 >> 5);
            sc2[nt][0] = pack_h2(rpb_s[off1 + ja], rpb_s[off1 + ja + 1]);
            sc2[nt][1] = pack_h2(rpb_s[off2 + ja], rpb_s[off2 + ja + 1]);
        }

        if (kt < 15) { CP_WAIT1(); } else { CP_WAIT0(); }
        __syncthreads();
        if (kt + 2 < 16) { copy_kv(kt + 2, (kt + 2) % 3); CP_COMMIT(); }

        const int s = kt % 3;
        char* Kb = dsm + AT_KS + s * 5120;
        char* Vb = dsm + AT_VS + s * 5120;

        // QK^T with fp16 accumulators (C layout == PV A-fragment layout)
#pragma unroll
        for (int ks = 0; ks < 2; ks++) {
#pragma unroll
            for (int q = 0; q < 4; q++) {
                uint32_t r[4];
                ldm_x4(r, smem_u32(Kb + (q * 16 + kb_row) * 80
                                      + (ks * 16 + kb_col) * 2));
                uint32_t b0[2] = { r[0], r[1] }, b1[2] = { r[2], r[3] };
                mma16816_h(sc2[2 * q],     aQ[ks], b0);
                mma16816_h(sc2[2 * q + 1], aQ[ks], b1);
            }
        }

        // p = 2^t directly on the fp16 MMA output registers
#pragma unroll
        for (int nt = 0; nt < 8; nt++) {
            __half2 e0 = h2exp2(*(__half2*)&sc2[nt][0]);
            __half2 e1 = h2exp2(*(__half2*)&sc2[nt][1]);
            sc2[nt][0] = *(uint32_t*)&e0;
            sc2[nt][1] = *(uint32_t*)&e1;
        }

        // P @ [V | 1]
#pragma unroll
        for (int kk = 0; kk < 4; kk++) {
            uint32_t aP[4] = { sc2[2 * kk][0], sc2[2 * kk][1],
                               sc2[2 * kk + 1][0], sc2[2 * kk + 1][1] };
#pragma unroll
            for (int dp = 0; dp < 2; dp++) {
                uint32_t r[4];
                ldm_x4_t(r, smem_u32(Vb + (kk * 16 + (lane & 15)) * 80
                                        + (dp * 16 + (lane >> 4) * 8) * 2));
                uint32_t b0[2] = { r[0], r[1] }, b1[2] = { r[2], r[3] };
                mma16816(oacc[2 * dp],     aP, b0);
                mma16816(oacc[2 * dp + 1], aP, b1);
            }
            mma16816(lacc, aP, bones);   // row-sum column (fp32 acc)
        }
    }

    // l lives in col 0 of the lacc tile -> lanes with lane%4==0; broadcast in quad
    float l1 = __shfl_sync(0xffffffffu, lacc[0], lane & ~3);
    float l2 = __shfl_sync(0xffffffffu, lacc[2], lane & ~3);

    float inv1 = 1.f / l1, inv2 = 1.f / l2;
#pragma unroll
    for (int ntd = 0; ntd < 4; ntd++) {
        int d0 = ntd * 8 + qc;
        *(__half2*)&g_oh[((size_t)b * NTOK + i1) * CH + h * HD + d0] =
            __floats2half2_rn(oacc[ntd][0] * inv1, oacc[ntd][1] * inv1);
        *(__half2*)&g_oh[((size_t)b * NTOK + i2) * CH + h * HD + d0] =
            __floats2half2_rn(oacc[ntd][2] * inv2, oacc[ntd][3] * inv2);
    }
}

// ---------------------------------------------------------------------------
extern "C" void kernel_launch(void* const* d_in, const int* in_sizes, int n_in,
                              void* d_out, int out_size)
{
    const float* x      = (const float*)d_in[0];
    const float* qkv_w  = (const float*)d_in[1];
    const float* qkv_b  = (const float*)d_in[2];
    const float* rpb    = (const float*)d_in[3];
    const float* proj_w = (const float*)d_in[4];
    const float* proj_b = (const float*)d_in[5];
    float* out = (float*)d_out;

    cudaFuncSetAttribute(hgemm, cudaFuncAttributeMaxDynamicSharedMemorySize, G_SMEM);
    cudaFuncSetAttribute(attn_kernel, cudaFuncAttributeMaxDynamicSharedMemorySize, AT_SMEM);

    convert_all<<<(NX4 + NWQ4 + NWP4 + 255) / 256, 256>>>(
        (const float4*)x, (const float4*)qkv_w, (const float4*)proj_w);
    hgemm<<<dim3(12, 64), 256, G_SMEM>>>(qkv_b, nullptr, 0);
    attn_kernel<<<dim3(BATCH * NHEAD, NTOK / 128), 256, AT_SMEM>>>(rpb);
    hgemm<<<dim3(4, 64), 256, G_SMEM>>>(proj_b, out, 1);
}

// round 17
// speedup vs baseline: 1.8973x; 1.0208x over previous
#include <cuda_runtime.h>
#include <cuda_fp16.h>
#include <cstdint>

#define BATCH 8
#define NTOK  1024
#define CH    512
#define NHEAD 16
#define HD    32
#define LOG2E 1.4426950408889634f
// q is pre-scaled by SCALE*log2e so QK^T lands in the 2^x domain
#define QSC (0.17677669529663689f * 1.4426950408889634f)

// fp16 scratch
__device__ __half g_xh[BATCH * NTOK * CH];
__device__ __half g_wqh[3 * CH * CH];
__device__ __half g_pwh[CH * CH];
__device__ __half g_q[BATCH * NHEAD * NTOK * HD];
__device__ __half g_k[BATCH * NHEAD * NTOK * HD];
__device__ __half g_v[BATCH * NHEAD * NTOK * HD];
__device__ __half g_oh[BATCH * NTOK * CH];

__device__ __forceinline__ uint32_t smem_u32(const void* p) {
    return (uint32_t)__cvta_generic_to_shared(p);
}
__device__ __forceinline__ void cp16(void* sdst, const void* gsrc) {
    asm volatile("cp.async.cg.shared.global [%0], [%1], 16;"
                 :: "r"(smem_u32(sdst)), "l"(gsrc));
}
#define CP_COMMIT() asm volatile("cp.async.commit_group;" ::: "memory")
#define CP_WAIT0()  asm volatile("cp.async.wait_group 0;" ::: "memory")
#define CP_WAIT1()  asm volatile("cp.async.wait_group 1;" ::: "memory")

__device__ __forceinline__ void ldm_x4(uint32_t* r, uint32_t a) {
    asm volatile("ldmatrix.sync.aligned.m8n8.x4.shared.b16 {%0,%1,%2,%3}, [%4];"
                 : "=r"(r[0]), "=r"(r[1]), "=r"(r[2]), "=r"(r[3]) : "r"(a));
}
__device__ __forceinline__ void ldm_x4_t(uint32_t* r, uint32_t a) {
    asm volatile("ldmatrix.sync.aligned.m8n8.x4.trans.shared.b16 {%0,%1,%2,%3}, [%4];"
                 : "=r"(r[0]), "=r"(r[1]), "=r"(r[2]), "=r"(r[3]) : "r"(a));
}
__device__ __forceinline__ void mma16816(float* c, const uint32_t* a, const uint32_t* b) {
    asm volatile(
        "mma.sync.aligned.m16n8k16.row.col.f32.f16.f16.f32 "
        "{%0,%1,%2,%3}, {%4,%5,%6,%7}, {%8,%9}, {%0,%1,%2,%3};"
        : "+f"(c[0]), "+f"(c[1]), "+f"(c[2]), "+f"(c[3])
        : "r"(a[0]), "r"(a[1]), "r"(a[2]), "r"(a[3]), "r"(b[0]), "r"(b[1]));
}
// fp16-accumulated variant: C = 2 packed half2 regs, layout == PV A-fragment
__device__ __forceinline__ void mma16816_h(uint32_t* c, const uint32_t* a, const uint32_t* b) {
    asm volatile(
        "mma.sync.aligned.m16n8k16.row.col.f16.f16.f16.f16 "
        "{%0,%1}, {%2,%3,%4,%5}, {%6,%7}, {%0,%1};"
        : "+r"(c[0]), "+r"(c[1])
        : "r"(a[0]), "r"(a[1]), "r"(a[2]), "r"(a[3]), "r"(b[0]), "r"(b[1]));
}
__device__ __forceinline__ uint32_t pack_h2(float x, float y) {
    __half2 h = __floats2half2_rn(x, y);
    return *(uint32_t*)&h;
}

// ---------------------------------------------------------------------------
// Kernel 0: fp32 -> fp16 conversion of X, qkv_w, proj_w.
// ---------------------------------------------------------------------------
#define NX4  (BATCH * NTOK * CH / 4)
#define NWQ4 (3 * CH * CH / 4)
#define NWP4 (CH * CH / 4)

__global__ __launch_bounds__(256) void convert_all(const float4* __restrict__ X,
                                                   const float4* __restrict__ Wq,
                                                   const float4* __restrict__ Wp)
{
    int i = blockIdx.x * 256 + threadIdx.x;
    const float4* src;
    __half2* dst;
    int j;
    if (i < NX4)                    { src = X;  dst = (__half2*)g_xh;  j = i; }
    else if (i < NX4 + NWQ4)        { src = Wq; dst = (__half2*)g_wqh; j = i - NX4; }
    else if (i < NX4 + NWQ4 + NWP4) { src = Wp; dst = (__half2*)g_pwh; j = i - NX4 - NWQ4; }
    else return;
    float4 v = __ldg(src + j);
    dst[2 * j]     = __floats2half2_rn(v.x, v.y);
    dst[2 * j + 1] = __floats2half2_rn(v.z, v.w);
}

// ---------------------------------------------------------------------------
// HMMA GEMM: 128x128 tile, 8 warps (32x64 each), K-chunk 32, 3-stage cp.async
// ring with ONE __syncthreads per K-iteration.  (Best measured configuration.)
// ---------------------------------------------------------------------------
#define GA_STAGE 10240
#define GB_BASE  30720
#define G_SMEM   61440

__global__ __launch_bounds__(256) void hgemm(const float* __restrict__ bias,
                                             float* __restrict__ out32,
                                             int mode)
{
    extern __shared__ __align__(16) char dsm[];

    const __half* Aptr = mode ? g_oh  : g_xh;
    const __half* Bptr = mode ? g_pwh : g_wqh;

    const int tid = threadIdx.x, lane = tid & 31, w = tid >> 5;
    const int wm = w >> 1, wn = w & 1;
    const int m0 = blockIdx.y * 128, n0 = blockIdx.x * 128;

    float acc[2][8][4];
#pragma unroll
    for (int mt = 0; mt < 2; mt++)
#pragma unroll
        for (int nt = 0; nt < 8; nt++)
#pragma unroll
            for (int c = 0; c < 4; c++) acc[mt][nt][c] = 0.f;

    const int a_row  = wm * 32 + (lane & 15);
    const int a_colh = (lane >> 4) * 8;
    const int b_row  = wn * 64 + (lane & 7) + ((lane >> 4) << 3);
    const int b_colh = ((lane >> 3) & 1) * 8;

    const int cr = tid >> 2, cc = (tid & 3) * 8;

    auto docopy = [&](int kc, int s) {
        char* Ab = dsm + s * GA_STAGE;
        char* Bb = dsm + GB_BASE + s * GA_STAGE;
#pragma unroll
        for (int i = 0; i < 2; i++) {
            int r = cr + i * 64;
            cp16(Ab + r * 80 + cc * 2, Aptr + (size_t)(m0 + r) * CH + kc * 32 + cc);
            cp16(Bb + r * 80 + cc * 2, Bptr + (size_t)(n0 + r) * CH + kc * 32 + cc);
        }
    };

    docopy(0, 0); CP_COMMIT();
    docopy(1, 1); CP_COMMIT();

    for (int kc = 0; kc < 16; kc++) {
        if (kc < 15) { CP_WAIT1(); } else { CP_WAIT0(); }
        __syncthreads();
        if (kc + 2 < 16) { docopy(kc + 2, (kc + 2) % 3); CP_COMMIT(); }

        const int s = kc % 3;
        char* Ab = dsm + s * GA_STAGE;
        char* Bb = dsm + GB_BASE + s * GA_STAGE;
#pragma unroll
        for (int ks = 0; ks < 2; ks++) {
            uint32_t aF[2][4];
#pragma unroll
            for (int mt = 0; mt < 2; mt++)
                ldm_x4(aF[mt], smem_u32(Ab + (a_row + mt * 16) * 80
                                           + (ks * 16 + a_colh) * 2));
            uint32_t bF[8][2];
#pragma unroll
            for (int q = 0; q < 4; q++) {
                uint32_t r[4];
                ldm_x4(r, smem_u32(Bb + (b_row + q * 16) * 80
                                      + (ks * 16 + b_colh) * 2));
                bF[2 * q][0] = r[0]; bF[2 * q][1] = r[1];
                bF[2 * q + 1][0] = r[2]; bF[2 * q + 1][1] = r[3];
            }
#pragma unroll
            for (int mt = 0; mt < 2; mt++)
#pragma unroll
                for (int nt = 0; nt < 8; nt++)
                    mma16816(acc[mt][nt], aF[mt], bF[nt]);
        }
    }

    const int qr = lane >> 2, qc = (lane & 3) * 2;
    if (mode == 0) {
#pragma unroll
        for (int mt = 0; mt < 2; mt++) {
#pragma unroll
            for (int nt = 0; nt < 8; nt++) {
                int jj = n0 + wn * 64 + nt * 8 + qc;
                float b0 = __ldg(&bias[jj]), b1 = __ldg(&bias[jj + 1]);
                int which = jj >> 9, h = (jj >> 5) & 15, dd = jj & 31;
#pragma unroll
                for (int rr = 0; rr < 2; rr++) {
                    int m = m0 + wm * 32 + mt * 16 + qr + rr * 8;
                    int b = m >> 10, n = m & 1023;
                    float v0 = acc[mt][nt][rr * 2 + 0] + b0;
                    float v1 = acc[mt][nt][rr * 2 + 1] + b1;
                    if (which == 0) { v0 *= QSC; v1 *= QSC; }   // fold log2e into q
                    __half2 hv = __floats2half2_rn(v0, v1);
                    size_t off = ((size_t)(b * NHEAD + h) * NTOK + n) * HD + dd;
                    if (which == 0)      *(__half2*)&g_q[off] = hv;
                    else if (which == 1) *(__half2*)&g_k[off] = hv;
                    else                 *(__half2*)&g_v[off] = hv;
                }
            }
        }
    } else {
#pragma unroll
        for (int mt = 0; mt < 2; mt++) {
#pragma unroll
            for (int nt = 0; nt < 8; nt++) {
                int jj = n0 + wn * 64 + nt * 8 + qc;
                float b0 = __ldg(&bias[jj]), b1 = __ldg(&bias[jj + 1]);
#pragma unroll
                for (int rr = 0; rr < 2; rr++) {
                    int m = m0 + wm * 32 + mt * 16 + qr + rr * 8;
                    float2 v = make_float2(acc[mt][nt][rr * 2 + 0] + b0,
                                           acc[mt][nt][rr * 2 + 1] + b1);
                    *(float2*)&out32[(size_t)m * CH + jj] = v;
                }
            }
        }
    }
}

// ---------------------------------------------------------------------------
// Kernel 2: attention, 8 warps / 128 queries per block, 3-stage cp.async
// K/V ring.  Log2-domain softmax with fp16-accumulated QK^T.
// NEW: all 8 V ldmatrix.trans loads hoisted to right after the barrier —
// independent of QK/exp, their latency completes under the QK phase, leaving
// the post-exp region a pure 20-MMA dependency-free stream.
// ---------------------------------------------------------------------------
#define AT_QS   0
#define AT_KS   10240
#define AT_VS   25600
#define AT_RPB  40960
#define AT_SMEM 56960

__global__ __launch_bounds__(256) void attn_kernel(const float* __restrict__ rpb)
{
    extern __shared__ __align__(16) char dsm[];
    __half* Qs    = (__half*)(dsm + AT_QS);
    float*  rpb_s = (float*)(dsm + AT_RPB);

    const int bh = blockIdx.x;
    const int b  = bh >> 4, h = bh & 15;
    const int qbase = blockIdx.y * 128;
    const int tid = threadIdx.x, lane = tid & 31, w = tid >> 5;

    const int cr = tid >> 2, cc = (tid & 3) * 8;
    const __half* kbase = g_k + (size_t)bh * NTOK * HD;
    const __half* vbase = g_v + (size_t)bh * NTOK * HD;

    auto copy_kv = [&](int kt, int s) {
        char* Kb = dsm + AT_KS + s * 5120;
        char* Vb = dsm + AT_VS + s * 5120;
        cp16(Kb + cr * 80 + cc * 2, kbase + (size_t)(kt * 64 + cr) * HD + cc);
        cp16(Vb + cr * 80 + cc * 2, vbase + (size_t)(kt * 64 + cr) * HD + cc);
    };

    copy_kv(0, 0); CP_COMMIT();
    copy_kv(1, 1); CP_COMMIT();

    // bias pre-scaled by log2e so exp becomes pure 2^x
    for (int e = tid; e < 3969; e += 256)
        rpb_s[e] = __ldg(rpb + (size_t)h * 3969 + e) * LOG2E;

    const __half* qg = g_q + ((size_t)bh * NTOK + qbase) * HD;
#pragma unroll
    for (int i = 0; i < 2; i++) {
        int e = tid + i * 256;
        int row = e >> 2, c8 = (e & 3) * 8;
        *(uint4*)(Qs + row * 40 + c8) = *(const uint4*)(qg + row * HD + c8);
    }
    __syncthreads();

    uint32_t aQ[2][4];
#pragma unroll
    for (int ks = 0; ks < 2; ks++)
        ldm_x4(aQ[ks], smem_u32(Qs + (w * 16 + (lane & 15)) * 40
                                   + ks * 16 + (lane >> 4) * 8));

    const int qr = lane >> 2, qc = (lane & 3) * 2;
    const int i1 = qbase + w * 16 + qr, i2 = i1 + 8;
    const int off1 = (31 - (i1 >> 5)) * 63 + (31 - (i1 & 31));
    const int off2 = (31 - (i2 >> 5)) * 63 + (31 - (i2 & 31));

    float oacc[4][4];
    float lacc[4];
#pragma unroll
    for (int i = 0; i < 4; i++) {
        lacc[i] = 0.f;
#pragma unroll
        for (int c = 0; c < 4; c++) oacc[i][c] = 0.f;
    }

    // ones-column B fragment: col 0 of an n8 tile = 1.0 for all k
    uint32_t bones[2];
    bones[0] = bones[1] = (lane < 4) ? 0x3C003C00u : 0u;

    const int kb_row = (lane & 7) + ((lane >> 4) << 3);
    const int kb_col = ((lane >> 3) & 1) * 8;

    for (int kt = 0; kt < 16; kt++) {
        // ---- C-init (bias, half2-packed) BEFORE the wait: hides pack+LDS ----
        uint32_t sc2[8][2];
#pragma unroll
        for (int nt = 0; nt < 8; nt++) {
            int j0 = kt * 64 + nt * 8 + qc;
            int ja = j0 + 31 * (j0 >> 5);
            sc2[nt][0] = pack_h2(rpb_s[off1 + ja], rpb_s[off1 + ja + 1]);
            sc2[nt][1] = pack_h2(rpb_s[off2 + ja], rpb_s[off2 + ja + 1]);
        }

        if (kt < 15) { CP_WAIT1(); } else { CP_WAIT0(); }
        __syncthreads();
        if (kt + 2 < 16) { copy_kv(kt + 2, (kt + 2) % 3); CP_COMMIT(); }

        const int s = kt % 3;
        char* Kb = dsm + AT_KS + s * 5120;
        char* Vb = dsm + AT_VS + s * 5120;

        // ---- hoisted V fragment loads (independent of QK/exp) ----
        uint32_t vF[4][2][4];
#pragma unroll
        for (int kk = 0; kk < 4; kk++)
#pragma unroll
            for (int dp = 0; dp < 2; dp++)
                ldm_x4_t(vF[kk][dp], smem_u32(Vb + (kk * 16 + (lane & 15)) * 80
                                                 + (dp * 16 + (lane >> 4) * 8) * 2));

        // QK^T with fp16 accumulators (C layout == PV A-fragment layout)
#pragma unroll
        for (int ks = 0; ks < 2; ks++) {
#pragma unroll
            for (int q = 0; q < 4; q++) {
                uint32_t r[4];
                ldm_x4(r, smem_u32(Kb + (q * 16 + kb_row) * 80
                                      + (ks * 16 + kb_col) * 2));
                uint32_t b0[2] = { r[0], r[1] }, b1[2] = { r[2], r[3] };
                mma16816_h(sc2[2 * q],     aQ[ks], b0);
                mma16816_h(sc2[2 * q + 1], aQ[ks], b1);
            }
        }

        // p = 2^t directly on the fp16 MMA output registers
#pragma unroll
        for (int nt = 0; nt < 8; nt++) {
            __half2 e0 = h2exp2(*(__half2*)&sc2[nt][0]);
            __half2 e1 = h2exp2(*(__half2*)&sc2[nt][1]);
            sc2[nt][0] = *(uint32_t*)&e0;
            sc2[nt][1] = *(uint32_t*)&e1;
        }

        // P @ [V | 1]  -- pure MMA stream, operands all register-resident
#pragma unroll
        for (int kk = 0; kk < 4; kk++) {
            uint32_t aP[4] = { sc2[2 * kk][0], sc2[2 * kk][1],
                               sc2[2 * kk + 1][0], sc2[2 * kk + 1][1] };
#pragma unroll
            for (int dp = 0; dp < 2; dp++) {
                uint32_t b0[2] = { vF[kk][dp][0], vF[kk][dp][1] };
                uint32_t b1[2] = { vF[kk][dp][2], vF[kk][dp][3] };
                mma16816(oacc[2 * dp],     aP, b0);
                mma16816(oacc[2 * dp + 1], aP, b1);
            }
            mma16816(lacc, aP, bones);   // row-sum column (fp32 acc)
        }
    }

    // l lives in col 0 of the lacc tile -> lanes with lane%4==0; broadcast in quad
    float l1 = __shfl_sync(0xffffffffu, lacc[0], lane & ~3);
    float l2 = __shfl_sync(0xffffffffu, lacc[2], lane & ~3);

    float inv1 = 1.f / l1, inv2 = 1.f / l2;
#pragma unroll
    for (int ntd = 0; ntd < 4; ntd++) {
        int d0 = ntd * 8 + qc;
        *(__half2*)&g_oh[((size_t)b * NTOK + i1) * CH + h * HD + d0] =
            __floats2half2_rn(oacc[ntd][0] * inv1, oacc[ntd][1] * inv1);
        *(__half2*)&g_oh[((size_t)b * NTOK + i2) * CH + h * HD + d0] =
            __floats2half2_rn(oacc[ntd][2] * inv2, oacc[ntd][3] * inv2);
    }
}

// ---------------------------------------------------------------------------
extern "C" void kernel_launch(void* const* d_in, const int* in_sizes, int n_in,
                              void* d_out, int out_size)
{
    const float* x      = (const float*)d_in[0];
    const float* qkv_w  = (const float*)d_in[1];
    const float* qkv_b  = (const float*)d_in[2];
    const float* rpb    = (const float*)d_in[3];
    const float* proj_w = (const float*)d_in[4];
    const float* proj_b = (const float*)d_in[5];
    float* out = (float*)d_out;

    cudaFuncSetAttribute(hgemm, cudaFuncAttributeMaxDynamicSharedMemorySize, G_SMEM);
    cudaFuncSetAttribute(attn_kernel, cudaFuncAttributeMaxDynamicSharedMemorySize, AT_SMEM);

    convert_all<<<(NX4 + NWQ4 + NWP4 + 255) / 256, 256>>>(
        (const float4*)x, (const float4*)qkv_w, (const float4*)proj_w);
    hgemm<<<dim3(12, 64), 256, G_SMEM>>>(qkv_b, nullptr, 0);
    attn_kernel<<<dim3(BATCH * NHEAD, NTOK / 128), 256, AT_SMEM>>>(rpb);
    hgemm<<<dim3(4, 64), 256, G_SMEM>>>(proj_b, out, 1);
}